// round 16
// baseline (speedup 1.0000x reference)
#include <cuda_runtime.h>
#include <math.h>

#define SUB1 15
#define T_MAX 120000

// ---------------- scratch (device globals — no allocs allowed) ----------------
__device__ float  g_syn[T_MAX * 32];      // interleaved {e,i} per (t,s): [t][s][2], s-pitch 32
__device__ float2 g_wei[105 * 16];        // [d][s] {ke, ki}
__device__ float2 g_whz[105 * 16];        // [d][s] {kh, ko}   (obs taps 0..103)
__device__ float  g_koh[105 * 16];        // [d][s] ko[104+d]  (obs taps 104..207)

// ---------------- basis functions (fp32, MUFU-fast) ----------------
__device__ __forceinline__ float cos_basis_f(int b, int d) {
    const float PI_F = 3.14159265358979f;
    float raw = 5.0f * logf((float)d + 1.0f + 1e-8f);
    float phi = 1.5707963267948966f * (float)b;
    if (raw < phi - PI_F || raw > phi + PI_F) return 0.f;
    return 0.5f * cosf(raw - phi) + 0.5f;
}

__device__ __forceinline__ float obs_basis_f(int b, int x) {
    const float PI_F = 3.14159265358979f;
    float phi;
    if (b == 0) {
        phi = 0.f;
    } else if (b & 1) {           // positive-side basis (x >= 0)
        if (x < 0) return 0.f;
        phi = 1.5707963267948966f * (float)((b + 1) >> 1);
    } else {                      // negative-side basis (x <= 0)
        if (x > 0) return 0.f;
        phi = 1.5707963267948966f * (float)(b >> 1);
    }
    float r = 5.0f * logf(fabsf((float)x) + 1.0f + 1e-8f);
    if (r < phi - PI_F || r > phi + PI_F) return 0.f;
    return 0.5f * cosf(r - phi) + 0.5f;
}

// ---------------- kernel precompute, run by block 0 of the fused mm launch ----------------
// Writes weights in [d][s] layout (coalesced for the conv's warp access pattern).
__device__ void prep_body(int tid, const float* __restrict__ W_syn,
                          const float* __restrict__ W_hist,
                          const float* __restrict__ W_obs) {
    for (int idx = tid; idx < SUB1 * 105; idx += 256) {
        int s = idx / 105, d = idx % 105;
        float ke = 0.f, ki = 0.f, kh = 0.f, ko = 0.f, ko2 = 0.f;
        if (d < 100) {
            for (int b = 0; b < 13; b++) {
                float bf = cos_basis_f(b, d);
                ke = fmaf(W_syn[(s * 13 + b) * 2 + 0], bf, ke);
                ki = fmaf(W_syn[(s * 13 + b) * 2 + 1], bf, ki);
                kh = fmaf(W_hist[s * 13 + b], bf, kh);
            }
        }
        if (d < 104) {  // obs tap j = d, x = j - 100
            for (int b = 0; b < 25; b++)
                ko = fmaf(W_obs[s * 25 + b], obs_basis_f(b, d - 100), ko);
        }
        if (d <= 96) {  // obs tap j = 104 + d, x = d + 4  (j <= 200)
            for (int b = 0; b < 25; b++)
                ko2 = fmaf(W_obs[s * 25 + b], obs_basis_f(b, d + 4), ko2);
        }
        g_wei[d * 16 + s] = make_float2(ke, ki);
        g_whz[d * 16 + s] = make_float2(kh, ko);
        g_koh[d * 16 + s] = ko2;
    }
}

// ---------------- helpers ----------------
__device__ __forceinline__ unsigned smem_u32(const void* p) {
    return (unsigned)__cvta_generic_to_shared(p);
}
__device__ __forceinline__ void cp16(unsigned dst, const float* src, int sz) {
    asm volatile("cp.async.cg.shared.global [%0], [%1], 16, %2;" :: "r"(dst), "l"(src), "r"(sz));
}
__device__ __forceinline__ unsigned to_tf32(float x) {
    unsigned r;
    asm("cvt.rna.tf32.f32 %0, %1;" : "=r"(r) : "f"(x));
    return r;
}
__device__ __forceinline__ void mma_tf32(float* c, unsigned a0, unsigned a1, unsigned a2,
                                         unsigned a3, unsigned b0, unsigned b1) {
    asm volatile(
        "mma.sync.aligned.m16n8k8.row.col.f32.tf32.tf32.f32 "
        "{%0,%1,%2,%3}, {%4,%5,%6,%7}, {%8,%9}, {%0,%1,%2,%3};"
        : "+f"(c[0]), "+f"(c[1]), "+f"(c[2]), "+f"(c[3])
        : "r"(a0), "r"(a1), "r"(a2), "r"(a3), "r"(b0), "r"(b1));
}

// ---------------- tensor-core matmul: out[t*32 + 2s + ch] = sum_k S[t,k] * C[s+1,k] ----------
// tf32 mma.sync m16n8k8, 3-stage cp.async pipeline. 8 warps, 32 rows/warp, 256 rows/block.
template <int K, int KC, int TP>
__device__ __forceinline__ void mm_tc_body(const float* __restrict__ S,
                                           const float* __restrict__ C,
                                           float* __restrict__ out, int T,
                                           int ch, int row0, float* sm) {
    const int NK8 = K / 8;      // total k8 steps
    const int CK8 = KC / 8;     // k8 steps per chunk
    const int QR = KC / 4;      // 16B quads per row per chunk
    float* tile = sm;                           // [3][256][TP]
    uint2* bfrag = (uint2*)(sm + 3 * 256 * TP); // [NK8][2 ntiles][32 lanes]
    const int tid = threadIdx.x;
    const int lane = tid & 31, wid = tid >> 5;
    const int gid = lane >> 2, tg = lane & 3;
    const unsigned tile_s = smem_u32(tile);

#define MMTC_ISSUE(c)                                                                   \
    do {                                                                                \
        const int k0_ = (c) * KC;                                                       \
        const unsigned tb_ = tile_s + (unsigned)(((c) % 3) * 256 * TP * 4);             \
        _Pragma("unroll")                                                               \
        for (int it = 0; it < QR; it++) {                                               \
            int f = it * 256 + tid;                                                     \
            int r = f / QR, q = f % QR;                                                 \
            int row = row0 + r;                                                         \
            int sz = (row < T) ? 16 : 0;                                                \
            cp16(tb_ + (unsigned)((r * TP + 4 * q) * 4),                                \
                 S + (size_t)(row < T ? row : 0) * K + k0_ + 4 * q, sz);                \
        }                                                                               \
        asm volatile("cp.async.commit_group;");                                         \
    } while (0)

    MMTC_ISSUE(0);

    // Build B fragments (overlaps with chunk-0 cp.async): bfrag[k8][nt][lane] =
    // { tf32(C[(s+1)K + k8*8 + tg]), tf32(... + tg+4) },  s = 8*nt + gid
    for (int li = tid; li < NK8 * 2 * 32; li += 256) {
        int l = li & 31, nt = (li >> 5) & 1, k8 = li >> 6;
        int s = 8 * nt + (l >> 2);
        int k = k8 * 8 + (l & 3);
        uint2 v = make_uint2(0u, 0u);
        if (s < SUB1) {
            v.x = to_tf32(__ldg(C + (size_t)(s + 1) * K + k));
            v.y = to_tf32(__ldg(C + (size_t)(s + 1) * K + k + 4));
        }
        bfrag[li] = v;
    }

    MMTC_ISSUE(1);

    float acc[16];
#pragma unroll
    for (int i = 0; i < 16; i++) acc[i] = 0.f;

    const int nch = K / KC;
    for (int c = 0; c < nch; c++) {
        if (c + 2 < nch) {
            MMTC_ISSUE(c + 2);
            asm volatile("cp.async.wait_group 2;");
        } else if (c + 1 < nch) {
            asm volatile("cp.async.wait_group 1;");
        } else {
            asm volatile("cp.async.wait_group 0;");
        }
        __syncthreads();                    // chunk c (and, on c==0, bfrag) visible
        const float* tb = tile + (c % 3) * 256 * TP;
#pragma unroll
        for (int kk = 0; kk < CK8; kk++) {
            const int k8 = c * CK8 + kk;
            const float* ap = tb + (32 * wid + gid) * TP + kk * 8 + tg;
            unsigned a0 = to_tf32(ap[0]);
            unsigned a2 = to_tf32(ap[4]);
            unsigned a1 = to_tf32(ap[8 * TP]);
            unsigned a3 = to_tf32(ap[8 * TP + 4]);
            unsigned a4 = to_tf32(ap[16 * TP]);
            unsigned a6 = to_tf32(ap[16 * TP + 4]);
            unsigned a5 = to_tf32(ap[24 * TP]);
            unsigned a7 = to_tf32(ap[24 * TP + 4]);
            uint2 b0 = bfrag[(k8 * 2 + 0) * 32 + lane];
            uint2 b1 = bfrag[(k8 * 2 + 1) * 32 + lane];
            mma_tf32(acc + 0,  a0, a1, a2, a3, b0.x, b0.y);   // mtile0, ntile0
            mma_tf32(acc + 4,  a0, a1, a2, a3, b1.x, b1.y);   // mtile0, ntile1
            mma_tf32(acc + 8,  a4, a5, a6, a7, b0.x, b0.y);   // mtile1, ntile0
            mma_tf32(acc + 12, a4, a5, a6, a7, b1.x, b1.y);   // mtile1, ntile1
        }
        __syncthreads();                    // slot (c%3) free for reuse at iter c+1
    }
#undef MMTC_ISSUE

    // store: c0=(row gid, col 2tg), c1=+1col, c2=(row gid+8), c3 both
    const int tbase = row0 + 32 * wid + gid;
#pragma unroll
    for (int mt = 0; mt < 2; mt++) {
#pragma unroll
        for (int nt = 0; nt < 2; nt++) {
            const float* a = acc + (mt * 2 + nt) * 4;
            int s0 = 8 * nt + 2 * tg;
            int t0 = tbase + 16 * mt;
            if (t0 < T) {
                out[(size_t)t0 * 32 + 2 * s0 + ch] = a[0];
                if (s0 + 1 < SUB1) out[(size_t)t0 * 32 + 2 * (s0 + 1) + ch] = a[1];
            }
            int t1 = t0 + 8;
            if (t1 < T) {
                out[(size_t)t1 * 32 + 2 * s0 + ch] = a[2];
                if (s0 + 1 < SUB1) out[(size_t)t1 * 32 + 2 * (s0 + 1) + ch] = a[3];
            }
        }
    }
}

// Fused launch: block 0 = prep, blocks [1, nblk] = E matmul, rest = I matmul.
__global__ __launch_bounds__(256, 2) void mm_fused(
    const float* __restrict__ Se, const float* __restrict__ Si,
    const float* __restrict__ Ce, const float* __restrict__ Ci,
    float* __restrict__ out, int T, int nblk,
    const float* Wsyn, const float* Whist, const float* Wobs)
{
    extern __shared__ float sm[];
    const int bid = blockIdx.x;
    if (bid == 0) { prep_body(threadIdx.x, Wsyn, Whist, Wobs); return; }
    if (bid <= nblk) {
        mm_tc_body<800, 16, 20>(Se, Ce, out, T, 0, (bid - 1) * 256, sm);
    } else {
        mm_tc_body<200, 8, 12>(Si, Ci, out, T, 1, (bid - 1 - nblk) * 256, sm);
    }
}

// ---------------- fused sliding-window conv; weights via coalesced __ldg [d][s] ----------------
__device__ __forceinline__ void conv_fused(unsigned long long acc2[8], float accs[8],
                                           const float2* __restrict__ sei,
                                           const float2* __restrict__ hz,
                                           const float* __restrict__ zo,
                                           int s,
                                           int base_a, int base_b, int base_c) {
    unsigned long long ya[8], yb[8];
    float yc[8];
#pragma unroll
    for (int j = 0; j < 8; j++) {
        ya[j] = *(const unsigned long long*)(sei + (base_a + j) * 17);
        yb[j] = *(const unsigned long long*)(hz + (base_b + j) * 17);
        yc[j] = zo[base_c + j];
    }
    const unsigned long long* wap = (const unsigned long long*)g_wei + s;
    const unsigned long long* wbp = (const unsigned long long*)g_whz + s;
    const float* wcp = g_koh + s;
    unsigned long long wa = __ldg(wap);
    unsigned long long wb = __ldg(wbp);
    float wc = __ldg(wcp);
#pragma unroll 1
    for (int d0 = 0; d0 < 104; d0 += 8) {
#pragma unroll
        for (int dd = 0; dd < 8; dd++) {
            int d = d0 + dd;
            // prefetch next-tap weights (d+1 <= 104, in bounds; coalesced 128B line)
            unsigned long long wa_n = __ldg(wap + (d + 1) * 16);
            unsigned long long wb_n = __ldg(wbp + (d + 1) * 16);
            float wc_n = __ldg(wcp + (d + 1) * 16);
#pragma unroll
            for (int r = 0; r < 8; r++)
                asm("fma.rn.f32x2 %0, %1, %2, %0;" : "+l"(acc2[r]) : "l"(ya[(r - dd) & 7]), "l"(wa));
#pragma unroll
            for (int r = 0; r < 8; r++)
                asm("fma.rn.f32x2 %0, %1, %2, %0;" : "+l"(acc2[r]) : "l"(yb[(r - dd) & 7]), "l"(wb));
#pragma unroll
            for (int r = 0; r < 8; r++)
                accs[r] = fmaf(yc[(r - dd) & 7], wc, accs[r]);
            ya[(7 - dd) & 7] = *(const unsigned long long*)(sei + (base_a - d - 1) * 17);
            yb[(7 - dd) & 7] = *(const unsigned long long*)(hz + (base_b - d - 1) * 17);
            yc[(7 - dd) & 7] = zo[base_c - d - 1];
            wa = wa_n; wb = wb_n; wc = wc_n;
        }
    }
}

// out[t,s] = exp( conv_ei + conv_hist + conv_obs + Theta[s] )
__global__ __launch_bounds__(256, 3) void conv_kernel(const float* __restrict__ Z_obs,
                                                      const float* __restrict__ Z_hid,
                                                      const float* __restrict__ Theta,
                                                      float* __restrict__ out0,
                                                      float* __restrict__ out1,
                                                      int T) {
    extern __shared__ float sm[];
    float2* sei = (float2*)sm;             // [232][17]  {syn_e, syn_i}, origin t0-104
    float2* hz  = sei + 232 * 17;          // [232][17]  {Z_hid[u], Z_obs[u+101]}, origin t0-104
    float*  zo  = (float*)(hz + 232 * 17); // [232]      Z_obs, origin t0-108
    const int tid = threadIdx.x;
    const int t0 = blockIdx.x * 128;

    for (int li = tid; li < 232 * 16; li += 256) {
        int lt = li >> 4, s = li & 15;
        int t = t0 - 104 + lt;
        float2 v = make_float2(0.f, 0.f);
        if (s < SUB1 && t >= 0 && t < T) v = *(const float2*)(g_syn + (size_t)t * 32 + 2 * s);
        sei[lt * 17 + s] = v;
        float zh = (s < SUB1 && t >= 0 && t < T) ? Z_hid[(size_t)t * SUB1 + s] : 0.f;
        int uz = t + 101;
        float zb = (uz >= 0 && uz < T) ? Z_obs[uz] : 0.f;
        hz[lt * 17 + s] = make_float2(zh, zb);
    }
    for (int li = tid; li < 232; li += 256) {
        int t = t0 - 108 + li;
        zo[li] = (t >= 0 && t < T) ? Z_obs[t] : 0.f;
    }
    __syncthreads();

    const int s = tid & 15;
    const int trun = tid >> 4;
    if (s >= SUB1) return;   // no barriers after this point

    unsigned long long acc2[8];
#pragma unroll
    for (int r = 0; r < 8; r++) acc2[r] = 0ull;
    float accs[8];
    float th = __ldg(Theta + s);
#pragma unroll
    for (int r = 0; r < 8; r++) accs[r] = th;

    conv_fused(acc2, accs,
               sei + s, hz + s, zo, s,
               104 + trun * 8,    // ei:   sum_d {syn_e,syn_i}[t-d] * {ke,ki}[d]
               103 + trun * 8,    // hz:   sum_d {Z_hid[t-1-d], Z_obs[t+100-d]} * {kh,ko}[d]
               104 + trun * 8);   // obs:  sum_d Z_obs[t-4-d] * ko[104+d]

    const int tb = t0 + trun * 8;
#pragma unroll
    for (int r = 0; r < 8; r++) {
        int t = tb + r;
        if (t < T) {
            float lo, hi;
            asm("mov.b64 {%0,%1}, %2;" : "=f"(lo), "=f"(hi) : "l"(acc2[r]));
            float v = expf(lo + hi + accs[r]);
            out0[(size_t)t * SUB1 + s] = v;
            out1[(size_t)t * SUB1 + s] = v;
        }
    }
}

extern "C" void kernel_launch(void* const* d_in, const int* in_sizes, int n_in,
                              void* d_out, int out_size) {
    const float* S_e    = (const float*)d_in[0];
    const float* S_i    = (const float*)d_in[1];
    const float* Z_obs  = (const float*)d_in[2];
    const float* Z_hid  = (const float*)d_in[3];
    const float* C_e    = (const float*)d_in[4];
    const float* C_i    = (const float*)d_in[5];
    const float* W_syn  = (const float*)d_in[6];
    const float* W_hist = (const float*)d_in[7];
    const float* W_obs  = (const float*)d_in[8];
    const float* Theta  = (const float*)d_in[9];
    const int T = in_sizes[2];          // Z_obs element count

    float* out0 = (float*)d_out;
    float* out1 = (out_size >= 2 * T * SUB1) ? out0 + (size_t)T * SUB1 : out0;

    // mm smem (E config is max): tile 3*256*20*4 = 61,440 + bfrag 100*2*32*8 = 51,200
    const int smem_mm = 3 * 256 * 20 * 4 + 100 * 2 * 32 * 8;   // 112,640
    const int smem_conv = (2 * 232 * 17 * 2 + 232) * (int)sizeof(float);  // 64,032

    cudaFuncSetAttribute(mm_fused,    cudaFuncAttributeMaxDynamicSharedMemorySize, smem_mm);
    cudaFuncSetAttribute(conv_kernel, cudaFuncAttributeMaxDynamicSharedMemorySize, smem_conv);

    float* syn_ptr;
    cudaGetSymbolAddress((void**)&syn_ptr, g_syn);

    int nblk = (T + 255) / 256;
    mm_fused<<<2 * nblk + 1, 256, smem_mm>>>(S_e, S_i, C_e, C_i, syn_ptr, T, nblk,
                                             W_syn, W_hist, W_obs);

    int conv_blocks = (T + 127) / 128;
    conv_kernel<<<conv_blocks, 256, smem_conv>>>(Z_obs, Z_hid, Theta, out0, out1, T);
}